// round 14
// baseline (speedup 1.0000x reference)
#include <cuda_runtime.h>

// ---------------------------------------------------------------------------
// Problem constants
// ---------------------------------------------------------------------------
#define B_    64
#define T_    12
#define HOR_  12
#define NN_   1024
#define HH_   64

// Scratch layout (offsets in floats)
constexpr int OFF_S    = 0;                          // [2048,1024]: rows 0-1023 = A (tf32)
constexpr int OFF_M2   = OFF_S    + 1024 * 1024;     //   rows 1024-2047 = M2 = rn(2A^2 - I)
constexpr int OFF_X    = OFF_M2   + 1024 * 1024;     // [1024, 768]  (n, t*64+b)
constexpr int OFF_AX   = OFF_X    + 1024 * 768;
constexpr int OFF_A2X  = OFF_AX   + 1024 * 768;      // contiguous with AX (stacked out)
constexpr int OFF_Y    = OFF_A2X  + 1024 * 768;
constexpr int OFF_AY   = OFF_Y    + 1024 * 768;
constexpr int OFF_A2Y  = OFF_AY   + 1024 * 768;
constexpr int OFF_H    = OFF_A2Y  + 1024 * 768;      // [65536,64]
constexpr int OFF_AH   = OFF_H    + 4194304;
constexpr int OFF_A2H  = OFF_AH   + 4194304;         // contiguous with AH (stacked out)
constexpr int OFF_ZH   = OFF_A2H  + 4194304;
constexpr int OFF_AZH  = OFF_ZH   + 4194304;
constexpr int OFF_A2ZH = OFF_AZH  + 4194304;         // contiguous with AZH (stacked out)
constexpr int OFF_R    = OFF_A2ZH + 4194304;
constexpr int OFF_GO   = OFF_R    + 4194304;         // [65536]
constexpr int OFF_AGO  = OFF_GO   + 65536;
constexpr int OFF_A2GO = OFF_AGO  + 65536;
constexpr int SCRATCH_TOTAL = OFF_A2GO + 65536;

__device__ float g_scratch[SCRATCH_TOTAL];

__device__ __forceinline__ unsigned f2tf(float x) {
    unsigned u;
    asm("cvt.rna.tf32.f32 %0, %1;" : "=r"(u) : "f"(x));
    return u;
}
__device__ __forceinline__ float tfv(float x) {     // value rounded to tf32 grid
    return __uint_as_float(f2tf(x));
}

// ---------------------------------------------------------------------------
// A = softmax(relu(E @ E^T), axis=-1),  E: [1024, 8].  tf32-RN into S rows 0-1023.
// ---------------------------------------------------------------------------
__global__ void __launch_bounds__(256) build_A(const float* __restrict__ emb) {
    __shared__ float Es[1024 * 8];
    __shared__ float red[256];
    const int tid = threadIdx.x;
    for (int i = tid; i < 1024 * 8; i += 256) Es[i] = emb[i];
    __syncthreads();

    const int r = blockIdx.x;
    float er[8];
#pragma unroll
    for (int j = 0; j < 8; j++) er[j] = Es[r * 8 + j];

    float v[4];
    float mx = -1e30f;
#pragma unroll
    for (int i = 0; i < 4; i++) {
        const int c = tid + i * 256;
        float s = 0.f;
#pragma unroll
        for (int j = 0; j < 8; j++) s += er[j] * Es[c * 8 + j];
        s = fmaxf(s, 0.f);
        v[i] = s;
        mx = fmaxf(mx, s);
    }
    red[tid] = mx;
    __syncthreads();
    for (int o = 128; o > 0; o >>= 1) {
        if (tid < o) red[tid] = fmaxf(red[tid], red[tid + o]);
        __syncthreads();
    }
    mx = red[0];
    __syncthreads();

    float sum = 0.f;
#pragma unroll
    for (int i = 0; i < 4; i++) {
        v[i] = expf(v[i] - mx);
        sum += v[i];
    }
    red[tid] = sum;
    __syncthreads();
    for (int o = 128; o > 0; o >>= 1) {
        if (tid < o) red[tid] += red[tid + o];
        __syncthreads();
    }
    const float inv = 1.f / red[0];
#pragma unroll
    for (int i = 0; i < 4; i++)
        g_scratch[OFF_S + r * 1024 + tid + i * 256] = tfv(v[i] * inv);
}

// ---------------------------------------------------------------------------
// Node-major transposes of x and y_cov
// ---------------------------------------------------------------------------
__global__ void __launch_bounds__(256) make_XY(const float* __restrict__ x,
                                               const float* __restrict__ y) {
    const int idx = blockIdx.x * 256 + threadIdx.x;
    if (idx >= 1024 * 768) return;
    const int n = idx / 768, col = idx % 768;
    const int t = col >> 6, b = col & 63;
    g_scratch[OFF_X + idx] = x[(b * T_ + t) * NN_ + n];
    g_scratch[OFF_Y + idx] = y[(b * HOR_ + t) * NN_ + n];
}

__global__ void __launch_bounds__(256) zero_state() {
    const int i = blockIdx.x * 256 + threadIdx.x;
    if (i < 1048576)
        *(float4*)(g_scratch + OFF_H + i * 4) = make_float4(0.f, 0.f, 0.f, 0.f);
    if (i < 65536) {
        g_scratch[OFF_GO + i]   = 0.f;
        g_scratch[OFF_AGO + i]  = 0.f;
        g_scratch[OFF_A2GO + i] = 0.f;
    }
}

// ---------------------------------------------------------------------------
// TF32 stacked support GEMM:  C[rows,Nn] = S[rows,1024] @ B[1024,Nn]
//   mode 0: C = S@B          mode 2: C = rn(2*S@B - I)   (M2 build, Nn=1024)
// ---------------------------------------------------------------------------
#define KDIM 1024
#define NKIT 64

__device__ __forceinline__ void cp16(void* dst_smem, const void* src) {
    unsigned s = (unsigned)__cvta_generic_to_shared(dst_smem);
    asm volatile("cp.async.cg.shared.global [%0], [%1], 16;\n" ::"r"(s), "l"(src));
}
__device__ __forceinline__ void cp_commit() {
    asm volatile("cp.async.commit_group;\n" ::);
}
template <int Nwait>
__device__ __forceinline__ void cp_wait() {
    asm volatile("cp.async.wait_group %0;\n" ::"n"(Nwait));
}
__device__ __forceinline__ void mma_tf32(float* c, const unsigned* a,
                                         const unsigned* b) {
    asm volatile(
        "mma.sync.aligned.m16n8k8.row.col.f32.tf32.tf32.f32 "
        "{%0,%1,%2,%3}, {%4,%5,%6,%7}, {%8,%9}, {%0,%1,%2,%3};\n"
        : "+f"(c[0]), "+f"(c[1]), "+f"(c[2]), "+f"(c[3])
        : "r"(a[0]), "r"(a[1]), "r"(a[2]), "r"(a[3]), "r"(b[0]), "r"(b[1]));
}

__global__ void __launch_bounds__(256, 2) tf32_supp5(int offB, int offC,
                                                     int Nn, int mode) {
    __shared__ float As[2][128][20];   // S tile [m][k] (already tf32 values)
    __shared__ float Bs[2][16][136];   // B tile [k][n]

    const int tid = threadIdx.x;
    const int lane = tid & 31, wid = tid >> 5;
    const int wm = wid & 1, wn = wid >> 1;          // 2 x 4 warp grid
    const int row0 = blockIdx.y * 128, col0 = blockIdx.x * 128;

    const float* Ag = g_scratch + OFF_S;
    const float* Bg = g_scratch + offB;

    const int ar = tid >> 2;
    const int ac = (tid & 3) << 2;
    const int bk = tid >> 5;
    const int bn = (tid & 31) << 2;

    float acc[4][4][4];
#pragma unroll
    for (int i = 0; i < 4; i++)
#pragma unroll
        for (int j = 0; j < 4; j++)
#pragma unroll
            for (int q = 0; q < 4; q++) acc[i][j][q] = 0.f;

    {
        const float* Ap = Ag + (row0 + ar) * KDIM + ac;
        cp16(&As[0][ar][ac], Ap);
        cp16(&As[0][ar + 64][ac], Ap + 64 * KDIM);
        const float* Bp = Bg + bk * Nn + col0 + bn;
        cp16(&Bs[0][bk][bn], Bp);
        cp16(&Bs[0][bk + 8][bn], Bp + 8 * Nn);
        cp_commit();
    }

    for (int k0 = 0; k0 < NKIT; k0++) {
        const int cur = k0 & 1;
        if (k0 + 1 < NKIT) {
            const int nxt = cur ^ 1;
            const int kg = (k0 + 1) << 4;
            const float* Ap = Ag + (row0 + ar) * KDIM + kg + ac;
            cp16(&As[nxt][ar][ac], Ap);
            cp16(&As[nxt][ar + 64][ac], Ap + 64 * KDIM);
            const float* Bp = Bg + (kg + bk) * Nn + col0 + bn;
            cp16(&Bs[nxt][bk][bn], Bp);
            cp16(&Bs[nxt][bk + 8][bn], Bp + 8 * Nn);
            cp_commit();
            cp_wait<1>();
        } else {
            cp_wait<0>();
        }
        __syncthreads();

#pragma unroll
        for (int ks = 0; ks < 2; ks++) {
            const int ka = ks * 8 + (lane & 3);
            unsigned a[4][4], b[4][2];
#pragma unroll
            for (int mt = 0; mt < 4; mt++) {
                const int r = wm * 64 + mt * 16 + (lane >> 2);
                a[mt][0] = __float_as_uint(As[cur][r][ka]);
                a[mt][1] = __float_as_uint(As[cur][r + 8][ka]);
                a[mt][2] = __float_as_uint(As[cur][r][ka + 4]);
                a[mt][3] = __float_as_uint(As[cur][r + 8][ka + 4]);
            }
#pragma unroll
            for (int nt = 0; nt < 4; nt++) {
                const int c = wn * 32 + nt * 8 + (lane >> 2);
                b[nt][0] = f2tf(Bs[cur][ka][c]);
                b[nt][1] = f2tf(Bs[cur][ka + 4][c]);
            }
#pragma unroll
            for (int mt = 0; mt < 4; mt++)
#pragma unroll
                for (int nt = 0; nt < 4; nt++)
                    mma_tf32(acc[mt][nt], a[mt], b[nt]);
        }
        __syncthreads();
    }

    // epilogue
    float* Cm = g_scratch + offC;
#pragma unroll
    for (int mt = 0; mt < 4; mt++) {
        const int r = row0 + wm * 64 + mt * 16 + (lane >> 2);
#pragma unroll
        for (int nt = 0; nt < 4; nt++) {
            const int c = col0 + wn * 32 + nt * 8 + ((lane & 3) << 1);
            float2 v0 = make_float2(acc[mt][nt][0], acc[mt][nt][1]);
            float2 v1 = make_float2(acc[mt][nt][2], acc[mt][nt][3]);
            if (mode == 2) {
                v0.x = tfv(2.f * v0.x - (r == c ? 1.f : 0.f));
                v0.y = tfv(2.f * v0.y - (r == c + 1 ? 1.f : 0.f));
                v1.x = tfv(2.f * v1.x - (r + 8 == c ? 1.f : 0.f));
                v1.y = tfv(2.f * v1.y - (r + 8 == c + 1 ? 1.f : 0.f));
            }
            *(float2*)(Cm + r * Nn + c) = v0;
            *(float2*)(Cm + (r + 8) * Nn + c) = v1;
        }
    }
}

// ---------------------------------------------------------------------------
// Tensor-core gate GCN with DUAL hi/lo tf32 split (error ~2^-22, fp32-grade):
//   pre = sum_seg Hseg@Wseg  via  hi*hi + hi*lo + lo*hi  MMAs;
//   + rank-1 x/y + bias -> z,r ; ZH = z*Hold, R = r.
// 128 rows x 128 cols per CTA, 256 thr (8 warps 2x4), warp 64x32, K=192.
// ---------------------------------------------------------------------------
template <int NXC>
__global__ void __launch_bounds__(256, 2) gcn_gate4(
    int oh0, int oh1, int oh2, int ox0, int ox1, int ox2,
    int oy0, int oy1, int oy2, int str0, int off0, int str1, int off1,
    const float* __restrict__ W, const float* __restrict__ bias,
    int oHold, int oZH, int oR) {
    constexpr int CPK = NXC + 64;
    __shared__ float Ah[16][132], Al[16][132];   // [k][m]
    __shared__ float Wh[16][132], Wl[16][132];   // [k][n]
    __shared__ float Wx[3 * NXC][128];
    __shared__ float Xs[3][128];
    __shared__ float Ys[NXC == 2 ? 3 : 1][128];

    const int tid = threadIdx.x;
    const int lane = tid & 31, wid = tid >> 5;
    const int wm = wid & 1, wn = wid >> 1;
    const int row0 = blockIdx.x * 128;
    const float* hseg[3] = {g_scratch + oh0, g_scratch + oh1, g_scratch + oh2};
    const float* xseg[3] = {g_scratch + ox0, g_scratch + ox1, g_scratch + ox2};
    const float* yseg[3] = {g_scratch + oy0, g_scratch + oy1, g_scratch + oy2};

    for (int i = tid; i < 3 * NXC * 128; i += 256) {
        const int seg = i / (NXC * 128);
        const int c = (i >> 7) % NXC;
        const int n = i & 127;
        Wx[seg * NXC + c][n] = W[(seg * CPK + c) * 128 + n];
    }
    for (int i = tid; i < 3 * 128; i += 256) {
        const int seg = i >> 7, rl = i & 127;
        const int m = row0 + rl;
        Xs[seg][rl] = xseg[seg][(m >> 6) * str0 + off0 + (m & 63)];
        if (NXC == 2)
            Ys[seg][rl] = yseg[seg][(m >> 6) * str1 + off1 + (m & 63)];
    }

    const int ar = tid >> 2, ac = (tid & 3) << 2;   // A stage: rows ar, ar+64
    const int wr = tid >> 5, wc = (tid & 31) << 2;  // W stage: rows wr, wr+8

    float acc[4][4][4];
#pragma unroll
    for (int i = 0; i < 4; i++)
#pragma unroll
        for (int j = 0; j < 4; j++)
#pragma unroll
            for (int q = 0; q < 4; q++) acc[i][j][q] = 0.f;

    for (int kb = 0; kb < 12; kb++) {
        const int seg = kb >> 2;
        const int kin = (kb & 3) << 4;
        const float* Hs = hseg[seg];
        const float* Wp = W + (seg * CPK + NXC + kin) * 128;
        const float4 a0 = *(const float4*)(Hs + (row0 + ar) * 64 + kin + ac);
        const float4 a1 = *(const float4*)(Hs + (row0 + ar + 64) * 64 + kin + ac);
        const float4 w0 = *(const float4*)(Wp + wr * 128 + wc);
        const float4 w1 = *(const float4*)(Wp + (wr + 8) * 128 + wc);
        __syncthreads();
        {
            const float va[8] = {a0.x, a0.y, a0.z, a0.w, a1.x, a1.y, a1.z, a1.w};
#pragma unroll
            for (int i = 0; i < 4; i++) {
                float hi = tfv(va[i]);
                Ah[ac + i][ar] = hi;
                Al[ac + i][ar] = tfv(va[i] - hi);
                hi = tfv(va[4 + i]);
                Ah[ac + i][ar + 64] = hi;
                Al[ac + i][ar + 64] = tfv(va[4 + i] - hi);
            }
            const float vw[8] = {w0.x, w0.y, w0.z, w0.w, w1.x, w1.y, w1.z, w1.w};
#pragma unroll
            for (int i = 0; i < 4; i++) {
                float hi = tfv(vw[i]);
                Wh[wr][wc + i] = hi;
                Wl[wr][wc + i] = tfv(vw[i] - hi);
                hi = tfv(vw[4 + i]);
                Wh[wr + 8][wc + i] = hi;
                Wl[wr + 8][wc + i] = tfv(vw[4 + i] - hi);
            }
        }
        __syncthreads();
#pragma unroll
        for (int ks = 0; ks < 2; ks++) {
            const int ka = ks * 8 + (lane & 3);
            unsigned ah[4][4], al[4][4], bh[4][2], bl[4][2];
#pragma unroll
            for (int mt = 0; mt < 4; mt++) {
                const int r = wm * 64 + mt * 16 + (lane >> 2);
                ah[mt][0] = __float_as_uint(Ah[ka][r]);
                ah[mt][1] = __float_as_uint(Ah[ka][r + 8]);
                ah[mt][2] = __float_as_uint(Ah[ka + 4][r]);
                ah[mt][3] = __float_as_uint(Ah[ka + 4][r + 8]);
                al[mt][0] = __float_as_uint(Al[ka][r]);
                al[mt][1] = __float_as_uint(Al[ka][r + 8]);
                al[mt][2] = __float_as_uint(Al[ka + 4][r]);
                al[mt][3] = __float_as_uint(Al[ka + 4][r + 8]);
            }
#pragma unroll
            for (int nt = 0; nt < 4; nt++) {
                const int c = wn * 32 + nt * 8 + (lane >> 2);
                bh[nt][0] = __float_as_uint(Wh[ka][c]);
                bh[nt][1] = __float_as_uint(Wh[ka + 4][c]);
                bl[nt][0] = __float_as_uint(Wl[ka][c]);
                bl[nt][1] = __float_as_uint(Wl[ka + 4][c]);
            }
#pragma unroll
            for (int mt = 0; mt < 4; mt++)
#pragma unroll
                for (int nt = 0; nt < 4; nt++) {
                    mma_tf32(acc[mt][nt], ah[mt], bh[nt]);
                    mma_tf32(acc[mt][nt], ah[mt], bl[nt]);
                    mma_tf32(acc[mt][nt], al[mt], bh[nt]);
                }
        }
        __syncthreads();
    }

    const float* Hold = g_scratch + oHold;
    float* ZH = g_scratch + oZH;
    float* Rb = g_scratch + oR;
#pragma unroll
    for (int mt = 0; mt < 4; mt++) {
#pragma unroll
        for (int half = 0; half < 2; half++) {
            const int rl = wm * 64 + mt * 16 + (lane >> 2) + half * 8;
            const int m = row0 + rl;
#pragma unroll
            for (int nt = 0; nt < 4; nt++) {
                const int c0 = wn * 32 + nt * 8 + ((lane & 3) << 1);
#pragma unroll
                for (int q = 0; q < 2; q++) {
                    const int c = c0 + q;
                    float v = acc[mt][nt][half * 2 + q];
#pragma unroll
                    for (int seg = 0; seg < 3; seg++) {
                        v = fmaf(Xs[seg][rl], Wx[seg * NXC][c], v);
                        if (NXC == 2)
                            v = fmaf(Ys[seg][rl], Wx[seg * NXC + 1][c], v);
                    }
                    const float sg = 1.f / (1.f + expf(-(v + bias[c])));
                    if (c < 64)
                        ZH[m * 64 + c] = sg * Hold[m * 64 + c];
                    else
                        Rb[m * 64 + (c - 64)] = sg;
                }
            }
        }
    }
}

// ---------------------------------------------------------------------------
// Tensor-core update GCN with dual hi/lo split: hc = tanh(pre + rank-1 + bias);
//   H = r*H + (1-r)*hc.   128 rows x 64 cols, 8 warps 4x2, warp 32x32, K=192.
// ---------------------------------------------------------------------------
template <int NXC>
__global__ void __launch_bounds__(256, 2) gcn_upd4(
    int oh0, int oh1, int oh2, int ox0, int ox1, int ox2,
    int oy0, int oy1, int oy2, int str0, int off0, int str1, int off1,
    const float* __restrict__ W, const float* __restrict__ bias,
    int oH, int oR) {
    constexpr int CPK = NXC + 64;
    __shared__ float Ah[16][132], Al[16][132];   // [k][m]
    __shared__ float Wh[16][68], Wl[16][68];     // [k][n]
    __shared__ float Wx[3 * NXC][64];
    __shared__ float Xs[3][128];
    __shared__ float Ys[NXC == 2 ? 3 : 1][128];

    const int tid = threadIdx.x;
    const int lane = tid & 31, wid = tid >> 5;
    const int wm = wid & 3, wn = wid >> 2;
    const int row0 = blockIdx.x * 128;
    const float* hseg[3] = {g_scratch + oh0, g_scratch + oh1, g_scratch + oh2};
    const float* xseg[3] = {g_scratch + ox0, g_scratch + ox1, g_scratch + ox2};
    const float* yseg[3] = {g_scratch + oy0, g_scratch + oy1, g_scratch + oy2};

    for (int i = tid; i < 3 * NXC * 64; i += 256) {
        const int seg = i / (NXC * 64);
        const int c = (i >> 6) % NXC;
        const int n = i & 63;
        Wx[seg * NXC + c][n] = W[(seg * CPK + c) * 64 + n];
    }
    for (int i = tid; i < 3 * 128; i += 256) {
        const int seg = i >> 7, rl = i & 127;
        const int m = row0 + rl;
        Xs[seg][rl] = xseg[seg][(m >> 6) * str0 + off0 + (m & 63)];
        if (NXC == 2)
            Ys[seg][rl] = yseg[seg][(m >> 6) * str1 + off1 + (m & 63)];
    }

    const int ar = tid >> 2, ac = (tid & 3) << 2;
    const int uwr = tid >> 4, uwc = (tid & 15) << 2;   // W: 16 rows x 64 cols

    float acc[2][4][4];
#pragma unroll
    for (int i = 0; i < 2; i++)
#pragma unroll
        for (int j = 0; j < 4; j++)
#pragma unroll
            for (int q = 0; q < 4; q++) acc[i][j][q] = 0.f;

    for (int kb = 0; kb < 12; kb++) {
        const int seg = kb >> 2;
        const int kin = (kb & 3) << 4;
        const float* Hs = hseg[seg];
        const float* Wp = W + (seg * CPK + NXC + kin) * 64;
        const float4 a0 = *(const float4*)(Hs + (row0 + ar) * 64 + kin + ac);
        const float4 a1 = *(const float4*)(Hs + (row0 + ar + 64) * 64 + kin + ac);
        const float4 w0 = *(const float4*)(Wp + uwr * 64 + uwc);
        __syncthreads();
        {
            const float va[8] = {a0.x, a0.y, a0.z, a0.w, a1.x, a1.y, a1.z, a1.w};
#pragma unroll
            for (int i = 0; i < 4; i++) {
                float hi = tfv(va[i]);
                Ah[ac + i][ar] = hi;
                Al[ac + i][ar] = tfv(va[i] - hi);
                hi = tfv(va[4 + i]);
                Ah[ac + i][ar + 64] = hi;
                Al[ac + i][ar + 64] = tfv(va[4 + i] - hi);
            }
            const float vw[4] = {w0.x, w0.y, w0.z, w0.w};
#pragma unroll
            for (int i = 0; i < 4; i++) {
                const float hi = tfv(vw[i]);
                Wh[uwr][uwc + i] = hi;
                Wl[uwr][uwc + i] = tfv(vw[i] - hi);
            }
        }
        __syncthreads();
#pragma unroll
        for (int ks = 0; ks < 2; ks++) {
            const int ka = ks * 8 + (lane & 3);
            unsigned ah[2][4], al[2][4], bh[4][2], bl[4][2];
#pragma unroll
            for (int mt = 0; mt < 2; mt++) {
                const int r = wm * 32 + mt * 16 + (lane >> 2);
                ah[mt][0] = __float_as_uint(Ah[ka][r]);
                ah[mt][1] = __float_as_uint(Ah[ka][r + 8]);
                ah[mt][2] = __float_as_uint(Ah[ka + 4][r]);
                ah[mt][3] = __float_as_uint(Ah[ka + 4][r + 8]);
                al[mt][0] = __float_as_uint(Al[ka][r]);
                al[mt][1] = __float_as_uint(Al[ka][r + 8]);
                al[mt][2] = __float_as_uint(Al[ka + 4][r]);
                al[mt][3] = __float_as_uint(Al[ka + 4][r + 8]);
            }
#pragma unroll
            for (int nt = 0; nt < 4; nt++) {
                const int c = wn * 32 + nt * 8 + (lane >> 2);
                bh[nt][0] = __float_as_uint(Wh[ka][c]);
                bh[nt][1] = __float_as_uint(Wh[ka + 4][c]);
                bl[nt][0] = __float_as_uint(Wl[ka][c]);
                bl[nt][1] = __float_as_uint(Wl[ka + 4][c]);
            }
#pragma unroll
            for (int mt = 0; mt < 2; mt++)
#pragma unroll
                for (int nt = 0; nt < 4; nt++) {
                    mma_tf32(acc[mt][nt], ah[mt], bh[nt]);
                    mma_tf32(acc[mt][nt], ah[mt], bl[nt]);
                    mma_tf32(acc[mt][nt], al[mt], bh[nt]);
                }
        }
        __syncthreads();
    }

    float* H = g_scratch + oH;
    const float* Rb = g_scratch + oR;
#pragma unroll
    for (int mt = 0; mt < 2; mt++) {
#pragma unroll
        for (int half = 0; half < 2; half++) {
            const int rl = wm * 32 + mt * 16 + (lane >> 2) + half * 8;
            const int m = row0 + rl;
#pragma unroll
            for (int nt = 0; nt < 4; nt++) {
                const int c0 = wn * 32 + nt * 8 + ((lane & 3) << 1);
#pragma unroll
                for (int q = 0; q < 2; q++) {
                    const int c = c0 + q;
                    float v = acc[mt][nt][half * 2 + q];
#pragma unroll
                    for (int seg = 0; seg < 3; seg++) {
                        v = fmaf(Xs[seg][rl], Wx[seg * NXC][c], v);
                        if (NXC == 2)
                            v = fmaf(Ys[seg][rl], Wx[seg * NXC + 1][c], v);
                    }
                    const float hc = tanhf(v + bias[c]);
                    const float rv = Rb[m * 64 + c];
                    const float ho = H[m * 64 + c];
                    H[m * 64 + c] = rv * ho + (1.f - rv) * hc;
                }
            }
        }
    }
}

// ---------------------------------------------------------------------------
// Decoder projection: thread-per-row serial dot.
// ---------------------------------------------------------------------------
__global__ void __launch_bounds__(256) proj_kernel(const float* __restrict__ pW,
                                                   const float* __restrict__ pb,
                                                   int t, float* __restrict__ out) {
    __shared__ float pws[64];
    const int tid = threadIdx.x;
    if (tid < 64) pws[tid] = pW[tid];
    __syncthreads();
    const int row = blockIdx.x * 256 + tid;
    const float* Hp = g_scratch + OFF_H + row * 64;
    float s = 0.f;
#pragma unroll
    for (int q = 0; q < 16; q++) {
        const float4 h = *(const float4*)(Hp + q * 4);
        s += h.x * pws[q * 4] + h.y * pws[q * 4 + 1] +
             h.z * pws[q * 4 + 2] + h.w * pws[q * 4 + 3];
    }
    const float go = s + pb[0];
    g_scratch[OFF_GO + row] = go;
    const int n = row >> 6, b = row & 63;
    out[(b * HOR_ + t) * NN_ + n] = go;
}

// A@go = (A@H)@pW + pb ; T2@go = (T2@H)@pW + pb  (rows of A and T2 sum to 1).
__global__ void __launch_bounds__(256) proj_aux(const float* __restrict__ pW,
                                                const float* __restrict__ pb) {
    __shared__ float pws[64];
    const int tid = threadIdx.x;
    if (tid < 64) pws[tid] = pW[tid];
    __syncthreads();
    const int row = blockIdx.x * 256 + tid;
    const int src = (blockIdx.y == 0) ? OFF_AH : OFF_A2H;
    const int dst = (blockIdx.y == 0) ? OFF_AGO : OFF_A2GO;
    const float* Hp = g_scratch + src + row * 64;
    float s = 0.f;
#pragma unroll
    for (int q = 0; q < 16; q++) {
        const float4 h = *(const float4*)(Hp + q * 4);
        s += h.x * pws[q * 4] + h.y * pws[q * 4 + 1] +
             h.z * pws[q * 4 + 2] + h.w * pws[q * 4 + 3];
    }
    g_scratch[dst + row] = s + pb[0];
}

// ---------------------------------------------------------------------------
// Orchestration
// ---------------------------------------------------------------------------
extern "C" void kernel_launch(void* const* d_in, const int* in_sizes, int n_in,
                              void* d_out, int out_size) {
    (void)in_sizes; (void)n_in; (void)out_size;
    const float* x   = (const float*)d_in[0];
    const float* y   = (const float*)d_in[1];
    const float* emb = (const float*)d_in[2];
    const float* egW = (const float*)d_in[3];
    const float* egb = (const float*)d_in[4];
    const float* euW = (const float*)d_in[5];
    const float* eub = (const float*)d_in[6];
    const float* dgW = (const float*)d_in[7];
    const float* dgb = (const float*)d_in[8];
    const float* duW = (const float*)d_in[9];
    const float* dub = (const float*)d_in[10];
    const float* pW  = (const float*)d_in[11];
    const float* pb  = (const float*)d_in[12];
    float* out = (float*)d_out;

    build_A<<<1024, 256>>>(emb);
    // M2 = rn(2*A@A - I) into S rows 1024-2047 (only A rows as the A-side)
    tf32_supp5<<<dim3(8, 8), 256>>>(OFF_S, OFF_M2, 1024, 2);
    make_XY<<<3072, 256>>>(x, y);
    zero_state<<<4096, 256>>>();

    const dim3 gX(6, 16);    // stacked [2048,768] outputs
    const dim3 gH(32, 16);   // stacked [2048,4096] outputs

    // Support-propagated exogenous inputs for all timesteps (stacked: [AX;T2X]).
    tf32_supp5<<<gX, 256>>>(OFF_X, OFF_AX, 768, 0);
    tf32_supp5<<<gX, 256>>>(OFF_Y, OFF_AY, 768, 0);

    // ---------------- Encoder ----------------
    for (int t = 0; t < T_; t++) {
        tf32_supp5<<<gH, 256>>>(OFF_H, OFF_AH, 4096, 0);   // [AH; T2H]
        gcn_gate4<1><<<512, 256>>>(OFF_H, OFF_AH, OFF_A2H,
                                   OFF_X, OFF_AX, OFF_A2X,
                                   0, 0, 0, 768, t * 64, 0, 0,
                                   egW, egb, OFF_H, OFF_ZH, OFF_R);
        tf32_supp5<<<gH, 256>>>(OFF_ZH, OFF_AZH, 4096, 0); // [AZH; T2ZH]
        gcn_upd4<1><<<512, 256>>>(OFF_ZH, OFF_AZH, OFF_A2ZH,
                                  OFF_X, OFF_AX, OFF_A2X,
                                  0, 0, 0, 768, t * 64, 0, 0,
                                  euW, eub, OFF_H, OFF_R);
    }

    // ---------------- Decoder ----------------
    for (int t = 0; t < HOR_; t++) {
        tf32_supp5<<<gH, 256>>>(OFF_H, OFF_AH, 4096, 0);
        if (t > 0) {
            proj_aux<<<dim3(256, 2), 256>>>(pW, pb);
        }
        gcn_gate4<2><<<512, 256>>>(OFF_H, OFF_AH, OFF_A2H,
                                   OFF_GO, OFF_AGO, OFF_A2GO,
                                   OFF_Y, OFF_AY, OFF_A2Y,
                                   64, 0, 768, t * 64,
                                   dgW, dgb, OFF_H, OFF_ZH, OFF_R);
        tf32_supp5<<<gH, 256>>>(OFF_ZH, OFF_AZH, 4096, 0);
        gcn_upd4<2><<<512, 256>>>(OFF_ZH, OFF_AZH, OFF_A2ZH,
                                  OFF_GO, OFF_AGO, OFF_A2GO,
                                  OFF_Y, OFF_AY, OFF_A2Y,
                                  64, 0, 768, t * 64,
                                  duW, dub, OFF_H, OFF_R);
        proj_kernel<<<256, 256>>>(pW, pb, t, out);
    }
}

// round 17
// speedup vs baseline: 1.3213x; 1.3213x over previous
#include <cuda_runtime.h>

// ---------------------------------------------------------------------------
// Problem constants
// ---------------------------------------------------------------------------
#define B_    64
#define T_    12
#define HOR_  12
#define NN_   1024
#define HH_   64

// Scratch layout (offsets in floats)
constexpr int OFF_S    = 0;                          // [2048,1024]: rows 0-1023 = A (tf32)
constexpr int OFF_M2   = OFF_S    + 1024 * 1024;     //   rows 1024-2047 = M2 = rn(2A^2 - I)
constexpr int OFF_X    = OFF_M2   + 1024 * 1024;     // [1024, 768]  (n, t*64+b)
constexpr int OFF_AX   = OFF_X    + 1024 * 768;
constexpr int OFF_A2X  = OFF_AX   + 1024 * 768;      // contiguous with AX (stacked out)
constexpr int OFF_Y    = OFF_A2X  + 1024 * 768;
constexpr int OFF_AY   = OFF_Y    + 1024 * 768;
constexpr int OFF_A2Y  = OFF_AY   + 1024 * 768;
constexpr int OFF_H    = OFF_A2Y  + 1024 * 768;      // [65536,64]
constexpr int OFF_AH   = OFF_H    + 4194304;
constexpr int OFF_A2H  = OFF_AH   + 4194304;         // contiguous with AH (stacked out)
constexpr int OFF_ZH   = OFF_A2H  + 4194304;
constexpr int OFF_AZH  = OFF_ZH   + 4194304;
constexpr int OFF_A2ZH = OFF_AZH  + 4194304;         // contiguous with AZH (stacked out)
constexpr int OFF_R    = OFF_A2ZH + 4194304;
constexpr int OFF_GO   = OFF_R    + 4194304;         // [65536]
constexpr int OFF_AGO  = OFF_GO   + 65536;
constexpr int OFF_A2GO = OFF_AGO  + 65536;
constexpr int SCRATCH_TOTAL = OFF_A2GO + 65536;

__device__ float g_scratch[SCRATCH_TOTAL];

__device__ __forceinline__ unsigned f2tf(float x) {
    unsigned u;
    asm("cvt.rna.tf32.f32 %0, %1;" : "=r"(u) : "f"(x));
    return u;
}
__device__ __forceinline__ float tfv(float x) {     // value rounded to tf32 grid
    return __uint_as_float(f2tf(x));
}

// ---------------------------------------------------------------------------
// A = softmax(relu(E @ E^T), axis=-1),  E: [1024, 8].  tf32-RN into S rows 0-1023.
// ---------------------------------------------------------------------------
__global__ void __launch_bounds__(256) build_A(const float* __restrict__ emb) {
    __shared__ float Es[1024 * 8];
    __shared__ float red[256];
    const int tid = threadIdx.x;
    for (int i = tid; i < 1024 * 8; i += 256) Es[i] = emb[i];
    __syncthreads();

    const int r = blockIdx.x;
    float er[8];
#pragma unroll
    for (int j = 0; j < 8; j++) er[j] = Es[r * 8 + j];

    float v[4];
    float mx = -1e30f;
#pragma unroll
    for (int i = 0; i < 4; i++) {
        const int c = tid + i * 256;
        float s = 0.f;
#pragma unroll
        for (int j = 0; j < 8; j++) s += er[j] * Es[c * 8 + j];
        s = fmaxf(s, 0.f);
        v[i] = s;
        mx = fmaxf(mx, s);
    }
    red[tid] = mx;
    __syncthreads();
    for (int o = 128; o > 0; o >>= 1) {
        if (tid < o) red[tid] = fmaxf(red[tid], red[tid + o]);
        __syncthreads();
    }
    mx = red[0];
    __syncthreads();

    float sum = 0.f;
#pragma unroll
    for (int i = 0; i < 4; i++) {
        v[i] = expf(v[i] - mx);
        sum += v[i];
    }
    red[tid] = sum;
    __syncthreads();
    for (int o = 128; o > 0; o >>= 1) {
        if (tid < o) red[tid] += red[tid + o];
        __syncthreads();
    }
    const float inv = 1.f / red[0];
#pragma unroll
    for (int i = 0; i < 4; i++)
        g_scratch[OFF_S + r * 1024 + tid + i * 256] = tfv(v[i] * inv);
}

// ---------------------------------------------------------------------------
// Node-major transposes of x and y_cov
// ---------------------------------------------------------------------------
__global__ void __launch_bounds__(256) make_XY(const float* __restrict__ x,
                                               const float* __restrict__ y) {
    const int idx = blockIdx.x * 256 + threadIdx.x;
    if (idx >= 1024 * 768) return;
    const int n = idx / 768, col = idx % 768;
    const int t = col >> 6, b = col & 63;
    g_scratch[OFF_X + idx] = x[(b * T_ + t) * NN_ + n];
    g_scratch[OFF_Y + idx] = y[(b * HOR_ + t) * NN_ + n];
}

// Zeroes H plus the support outputs consumed at encoder t=0 (AH/A2H/AZH/A2ZH),
// allowing both t=0 support GEMMs (outputs identically zero) to be skipped.
__global__ void __launch_bounds__(256) zero_state() {
    const int i = blockIdx.x * 256 + threadIdx.x;   // 5*1048576 float4s
    const long total = 5L * 1048576L;
    if (i < total) {
        long off;
        if (i < 3 * 1048576) off = OFF_H + (long)i * 4;                 // H, AH, A2H
        else off = OFF_AZH + (long)(i - 3 * 1048576) * 4;               // AZH, A2ZH
        *(float4*)(g_scratch + off) = make_float4(0.f, 0.f, 0.f, 0.f);
    }
    if (i < 65536) {
        g_scratch[OFF_GO + i]   = 0.f;
        g_scratch[OFF_AGO + i]  = 0.f;
        g_scratch[OFF_A2GO + i] = 0.f;
    }
}

// ---------------------------------------------------------------------------
// TF32 stacked support GEMM:  C[rows,Nn] = S[rows,1024] @ B[1024,Nn]
//   mode 0: C = S@B          mode 2: C = rn(2*S@B - I)   (M2 build, Nn=1024)
// ---------------------------------------------------------------------------
#define KDIM 1024
#define NKIT 64

__device__ __forceinline__ void cp16(void* dst_smem, const void* src) {
    unsigned s = (unsigned)__cvta_generic_to_shared(dst_smem);
    asm volatile("cp.async.cg.shared.global [%0], [%1], 16;\n" ::"r"(s), "l"(src));
}
__device__ __forceinline__ void cp_commit() {
    asm volatile("cp.async.commit_group;\n" ::);
}
template <int Nwait>
__device__ __forceinline__ void cp_wait() {
    asm volatile("cp.async.wait_group %0;\n" ::"n"(Nwait));
}
__device__ __forceinline__ void mma_tf32(float* c, const unsigned* a,
                                         const unsigned* b) {
    asm volatile(
        "mma.sync.aligned.m16n8k8.row.col.f32.tf32.tf32.f32 "
        "{%0,%1,%2,%3}, {%4,%5,%6,%7}, {%8,%9}, {%0,%1,%2,%3};\n"
        : "+f"(c[0]), "+f"(c[1]), "+f"(c[2]), "+f"(c[3])
        : "r"(a[0]), "r"(a[1]), "r"(a[2]), "r"(a[3]), "r"(b[0]), "r"(b[1]));
}

__global__ void __launch_bounds__(256, 2) tf32_supp5(int offB, int offC,
                                                     int Nn, int mode) {
    __shared__ float As[2][128][20];   // S tile [m][k] (already tf32 values)
    __shared__ float Bs[2][16][136];   // B tile [k][n]

    const int tid = threadIdx.x;
    const int lane = tid & 31, wid = tid >> 5;
    const int wm = wid & 1, wn = wid >> 1;          // 2 x 4 warp grid
    const int row0 = blockIdx.y * 128, col0 = blockIdx.x * 128;

    const float* Ag = g_scratch + OFF_S;
    const float* Bg = g_scratch + offB;

    const int ar = tid >> 2;
    const int ac = (tid & 3) << 2;
    const int bk = tid >> 5;
    const int bn = (tid & 31) << 2;

    float acc[4][4][4];
#pragma unroll
    for (int i = 0; i < 4; i++)
#pragma unroll
        for (int j = 0; j < 4; j++)
#pragma unroll
            for (int q = 0; q < 4; q++) acc[i][j][q] = 0.f;

    {
        const float* Ap = Ag + (row0 + ar) * KDIM + ac;
        cp16(&As[0][ar][ac], Ap);
        cp16(&As[0][ar + 64][ac], Ap + 64 * KDIM);
        const float* Bp = Bg + bk * Nn + col0 + bn;
        cp16(&Bs[0][bk][bn], Bp);
        cp16(&Bs[0][bk + 8][bn], Bp + 8 * Nn);
        cp_commit();
    }

    for (int k0 = 0; k0 < NKIT; k0++) {
        const int cur = k0 & 1;
        if (k0 + 1 < NKIT) {
            const int nxt = cur ^ 1;
            const int kg = (k0 + 1) << 4;
            const float* Ap = Ag + (row0 + ar) * KDIM + kg + ac;
            cp16(&As[nxt][ar][ac], Ap);
            cp16(&As[nxt][ar + 64][ac], Ap + 64 * KDIM);
            const float* Bp = Bg + (kg + bk) * Nn + col0 + bn;
            cp16(&Bs[nxt][bk][bn], Bp);
            cp16(&Bs[nxt][bk + 8][bn], Bp + 8 * Nn);
            cp_commit();
            cp_wait<1>();
        } else {
            cp_wait<0>();
        }
        __syncthreads();

#pragma unroll
        for (int ks = 0; ks < 2; ks++) {
            const int ka = ks * 8 + (lane & 3);
            unsigned a[4][4], b[4][2];
#pragma unroll
            for (int mt = 0; mt < 4; mt++) {
                const int r = wm * 64 + mt * 16 + (lane >> 2);
                a[mt][0] = __float_as_uint(As[cur][r][ka]);
                a[mt][1] = __float_as_uint(As[cur][r + 8][ka]);
                a[mt][2] = __float_as_uint(As[cur][r][ka + 4]);
                a[mt][3] = __float_as_uint(As[cur][r + 8][ka + 4]);
            }
#pragma unroll
            for (int nt = 0; nt < 4; nt++) {
                const int c = wn * 32 + nt * 8 + (lane >> 2);
                b[nt][0] = f2tf(Bs[cur][ka][c]);
                b[nt][1] = f2tf(Bs[cur][ka + 4][c]);
            }
#pragma unroll
            for (int mt = 0; mt < 4; mt++)
#pragma unroll
                for (int nt = 0; nt < 4; nt++)
                    mma_tf32(acc[mt][nt], a[mt], b[nt]);
        }
        __syncthreads();
    }

    // epilogue
    float* Cm = g_scratch + offC;
#pragma unroll
    for (int mt = 0; mt < 4; mt++) {
        const int r = row0 + wm * 64 + mt * 16 + (lane >> 2);
#pragma unroll
        for (int nt = 0; nt < 4; nt++) {
            const int c = col0 + wn * 32 + nt * 8 + ((lane & 3) << 1);
            float2 v0 = make_float2(acc[mt][nt][0], acc[mt][nt][1]);
            float2 v1 = make_float2(acc[mt][nt][2], acc[mt][nt][3]);
            if (mode == 2) {
                v0.x = tfv(2.f * v0.x - (r == c ? 1.f : 0.f));
                v0.y = tfv(2.f * v0.y - (r == c + 1 ? 1.f : 0.f));
                v1.x = tfv(2.f * v1.x - (r + 8 == c ? 1.f : 0.f));
                v1.y = tfv(2.f * v1.y - (r + 8 == c + 1 ? 1.f : 0.f));
            }
            *(float2*)(Cm + r * Nn + c) = v0;
            *(float2*)(Cm + (r + 8) * Nn + c) = v1;
        }
    }
}

// ---------------------------------------------------------------------------
// Fused gate GCN (fp32, occupancy pinned to 2 CTA/SM):
//   out = sigmoid(sum_seg Hseg@Wh_seg + rank-1 x/y + bias); ZH = z*Hold, R = r.
// ---------------------------------------------------------------------------
template <int NXC>
__global__ void __launch_bounds__(256, 2) gcn_gate2(
    int oh0, int oh1, int oh2, int ox0, int ox1, int ox2,
    int oy0, int oy1, int oy2, int str0, int off0, int str1, int off1,
    const float* __restrict__ W, const float* __restrict__ bias,
    int oHold, int oZH, int oR) {
    constexpr int CPK = NXC + 64;
    __shared__ float As[16][132];
    __shared__ float Ws[16][128];
    __shared__ float Wx[3 * NXC][128];
    __shared__ float Xs[3][128];
    __shared__ float Ys[NXC == 2 ? 3 : 1][128];

    const int tid = threadIdx.x;
    const int row0 = blockIdx.x * 128;
    const float* hseg[3] = {g_scratch + oh0, g_scratch + oh1, g_scratch + oh2};
    const float* xseg[3] = {g_scratch + ox0, g_scratch + ox1, g_scratch + ox2};
    const float* yseg[3] = {g_scratch + oy0, g_scratch + oy1, g_scratch + oy2};

    for (int i = tid; i < 3 * NXC * 128; i += 256) {
        const int seg = i / (NXC * 128);
        const int c = (i >> 7) % NXC;
        const int n = i & 127;
        Wx[seg * NXC + c][n] = W[(seg * CPK + c) * 128 + n];
    }
    for (int i = tid; i < 3 * 128; i += 256) {
        const int seg = i >> 7, rl = i & 127;
        const int m = row0 + rl;
        Xs[seg][rl] = xseg[seg][(m >> 6) * str0 + off0 + (m & 63)];
        if (NXC == 2)
            Ys[seg][rl] = yseg[seg][(m >> 6) * str1 + off1 + (m & 63)];
    }

    const int ar = tid >> 2, ac = (tid & 3) << 2;    // A stage
    const int wr = tid >> 5, wc = (tid & 31) << 2;   // W stage
    const int tx = tid & 15, ty = tid >> 4;

    float acc[8][8];
#pragma unroll
    for (int i = 0; i < 8; i++)
#pragma unroll
        for (int j = 0; j < 8; j++) acc[i][j] = 0.f;

    for (int seg = 0; seg < 3; seg++) {
        const float* Hs = hseg[seg];
        const float* Wseg = W + (seg * CPK + NXC) * 128;
#pragma unroll
        for (int kt = 0; kt < 4; kt++) {
            const float4 a0 = *(const float4*)(Hs + (row0 + ar) * 64 + kt * 16 + ac);
            const float4 a1 = *(const float4*)(Hs + (row0 + ar + 64) * 64 + kt * 16 + ac);
            const float4 w0 = *(const float4*)(Wseg + (kt * 16 + wr) * 128 + wc);
            const float4 w1 = *(const float4*)(Wseg + (kt * 16 + wr + 8) * 128 + wc);
            __syncthreads();
            As[ac + 0][ar] = a0.x; As[ac + 1][ar] = a0.y;
            As[ac + 2][ar] = a0.z; As[ac + 3][ar] = a0.w;
            As[ac + 0][ar + 64] = a1.x; As[ac + 1][ar + 64] = a1.y;
            As[ac + 2][ar + 64] = a1.z; As[ac + 3][ar + 64] = a1.w;
            *(float4*)&Ws[wr][wc] = w0;
            *(float4*)&Ws[wr + 8][wc] = w1;
            __syncthreads();
#pragma unroll
            for (int k = 0; k < 16; k++) {
                const float4 xa = *(const float4*)&As[k][ty << 2];
                const float4 xb = *(const float4*)&As[k][64 + (ty << 2)];
                const float4 ya = *(const float4*)&Ws[k][tx << 2];
                const float4 yb = *(const float4*)&Ws[k][64 + (tx << 2)];
                const float ra[8] = {xa.x, xa.y, xa.z, xa.w, xb.x, xb.y, xb.z, xb.w};
                const float rb[8] = {ya.x, ya.y, ya.z, ya.w, yb.x, yb.y, yb.z, yb.w};
#pragma unroll
                for (int i = 0; i < 8; i++)
#pragma unroll
                    for (int j = 0; j < 8; j++)
                        acc[i][j] = fmaf(ra[i], rb[j], acc[i][j]);
            }
        }
    }

    const float* Hold = g_scratch + oHold;
    float* ZH = g_scratch + oZH;
    float* Rb = g_scratch + oR;
#pragma unroll
    for (int rr = 0; rr < 2; rr++)
#pragma unroll
        for (int ii = 0; ii < 4; ii++) {
            const int rl = rr * 64 + (ty << 2) + ii;
            const int m = row0 + rl;
            const int ai = rr * 4 + ii;
            float zh4[4], rv4[4];
#pragma unroll
            for (int j = 0; j < 4; j++) {
                const int c = (tx << 2) + j;
                float az = acc[ai][j], arr = acc[ai][4 + j];
#pragma unroll
                for (int seg = 0; seg < 3; seg++) {
                    az  = fmaf(Xs[seg][rl], Wx[seg * NXC][c], az);
                    arr = fmaf(Xs[seg][rl], Wx[seg * NXC][64 + c], arr);
                    if (NXC == 2) {
                        az  = fmaf(Ys[seg][rl], Wx[seg * NXC + 1][c], az);
                        arr = fmaf(Ys[seg][rl], Wx[seg * NXC + 1][64 + c], arr);
                    }
                }
                const float zv = 1.f / (1.f + expf(-(az + bias[c])));
                zh4[j] = zv * Hold[m * 64 + c];
                rv4[j] = 1.f / (1.f + expf(-(arr + bias[64 + c])));
            }
            *(float4*)(ZH + m * 64 + (tx << 2)) =
                make_float4(zh4[0], zh4[1], zh4[2], zh4[3]);
            *(float4*)(Rb + m * 64 + (tx << 2)) =
                make_float4(rv4[0], rv4[1], rv4[2], rv4[3]);
        }
}

// ---------------------------------------------------------------------------
// Fused update GCN (fp32): hc = tanh(...), H = r*H + (1-r)*hc.
// ---------------------------------------------------------------------------
template <int NXC>
__global__ void __launch_bounds__(256, 2) gcn_upd2(
    int oh0, int oh1, int oh2, int ox0, int ox1, int ox2,
    int oy0, int oy1, int oy2, int str0, int off0, int str1, int off1,
    const float* __restrict__ W, const float* __restrict__ bias,
    int oH, int oR) {
    constexpr int CPK = NXC + 64;
    __shared__ float As[16][132];
    __shared__ float Ws[16][64];
    __shared__ float Wx[3 * NXC][64];
    __shared__ float Xs[3][128];
    __shared__ float Ys[NXC == 2 ? 3 : 1][128];

    const int tid = threadIdx.x;
    const int row0 = blockIdx.x * 128;
    const float* hseg[3] = {g_scratch + oh0, g_scratch + oh1, g_scratch + oh2};
    const float* xseg[3] = {g_scratch + ox0, g_scratch + ox1, g_scratch + ox2};
    const float* yseg[3] = {g_scratch + oy0, g_scratch + oy1, g_scratch + oy2};

    for (int i = tid; i < 3 * NXC * 64; i += 256) {
        const int seg = i / (NXC * 64);
        const int c = (i >> 6) % NXC;
        const int n = i & 63;
        Wx[seg * NXC + c][n] = W[(seg * CPK + c) * 64 + n];
    }
    for (int i = tid; i < 3 * 128; i += 256) {
        const int seg = i >> 7, rl = i & 127;
        const int m = row0 + rl;
        Xs[seg][rl] = xseg[seg][(m >> 6) * str0 + off0 + (m & 63)];
        if (NXC == 2)
            Ys[seg][rl] = yseg[seg][(m >> 6) * str1 + off1 + (m & 63)];
    }

    const int ar = tid >> 2, ac = (tid & 3) << 2;
    const int uwr = tid >> 4, uwc = (tid & 15) << 2;
    const int tx = tid & 15, ty = tid >> 4;

    float acc[8][4];
#pragma unroll
    for (int i = 0; i < 8; i++)
#pragma unroll
        for (int j = 0; j < 4; j++) acc[i][j] = 0.f;

    for (int seg = 0; seg < 3; seg++) {
        const float* Hs = hseg[seg];
        const float* Wseg = W + (seg * CPK + NXC) * 64;
#pragma unroll
        for (int kt = 0; kt < 4; kt++) {
            const float4 a0 = *(const float4*)(Hs + (row0 + ar) * 64 + kt * 16 + ac);
            const float4 a1 = *(const float4*)(Hs + (row0 + ar + 64) * 64 + kt * 16 + ac);
            const float4 w0 = *(const float4*)(Wseg + (kt * 16 + uwr) * 64 + uwc);
            __syncthreads();
            As[ac + 0][ar] = a0.x; As[ac + 1][ar] = a0.y;
            As[ac + 2][ar] = a0.z; As[ac + 3][ar] = a0.w;
            As[ac + 0][ar + 64] = a1.x; As[ac + 1][ar + 64] = a1.y;
            As[ac + 2][ar + 64] = a1.z; As[ac + 3][ar + 64] = a1.w;
            *(float4*)&Ws[uwr][uwc] = w0;
            __syncthreads();
#pragma unroll
            for (int k = 0; k < 16; k++) {
                const float4 xa = *(const float4*)&As[k][ty << 2];
                const float4 xb = *(const float4*)&As[k][64 + (ty << 2)];
                const float4 yy = *(const float4*)&Ws[k][tx << 2];
                const float ra[8] = {xa.x, xa.y, xa.z, xa.w, xb.x, xb.y, xb.z, xb.w};
                const float rb[4] = {yy.x, yy.y, yy.z, yy.w};
#pragma unroll
                for (int i = 0; i < 8; i++)
#pragma unroll
                    for (int j = 0; j < 4; j++)
                        acc[i][j] = fmaf(ra[i], rb[j], acc[i][j]);
            }
        }
    }

    float* H = g_scratch + oH;
    const float* Rb = g_scratch + oR;
#pragma unroll
    for (int rr = 0; rr < 2; rr++)
#pragma unroll
        for (int ii = 0; ii < 4; ii++) {
            const int rl = rr * 64 + (ty << 2) + ii;
            const int m = row0 + rl;
            const int ai = rr * 4 + ii;
            float h4[4];
#pragma unroll
            for (int j = 0; j < 4; j++) {
                const int c = (tx << 2) + j;
                float ac_ = acc[ai][j];
#pragma unroll
                for (int seg = 0; seg < 3; seg++) {
                    ac_ = fmaf(Xs[seg][rl], Wx[seg * NXC][c], ac_);
                    if (NXC == 2)
                        ac_ = fmaf(Ys[seg][rl], Wx[seg * NXC + 1][c], ac_);
                }
                const float hc = tanhf(ac_ + bias[c]);
                const float rv = Rb[m * 64 + c];
                const float ho = H[m * 64 + c];
                h4[j] = rv * ho + (1.f - rv) * hc;
            }
            *(float4*)(H + m * 64 + (tx << 2)) =
                make_float4(h4[0], h4[1], h4[2], h4[3]);
        }
}

// ---------------------------------------------------------------------------
// Decoder projection: thread-per-row serial dot.
// ---------------------------------------------------------------------------
__global__ void __launch_bounds__(256) proj_kernel(const float* __restrict__ pW,
                                                   const float* __restrict__ pb,
                                                   int t, float* __restrict__ out) {
    __shared__ float pws[64];
    const int tid = threadIdx.x;
    if (tid < 64) pws[tid] = pW[tid];
    __syncthreads();
    const int row = blockIdx.x * 256 + tid;
    const float* Hp = g_scratch + OFF_H + row * 64;
    float s = 0.f;
#pragma unroll
    for (int q = 0; q < 16; q++) {
        const float4 h = *(const float4*)(Hp + q * 4);
        s += h.x * pws[q * 4] + h.y * pws[q * 4 + 1] +
             h.z * pws[q * 4 + 2] + h.w * pws[q * 4 + 3];
    }
    const float go = s + pb[0];
    g_scratch[OFF_GO + row] = go;
    const int n = row >> 6, b = row & 63;
    out[(b * HOR_ + t) * NN_ + n] = go;
}

// A@go = (A@H)@pW + pb ; T2@go = (T2@H)@pW + pb  (rows of A and T2 sum to 1).
__global__ void __launch_bounds__(256) proj_aux(const float* __restrict__ pW,
                                                const float* __restrict__ pb) {
    __shared__ float pws[64];
    const int tid = threadIdx.x;
    if (tid < 64) pws[tid] = pW[tid];
    __syncthreads();
    const int row = blockIdx.x * 256 + tid;
    const int src = (blockIdx.y == 0) ? OFF_AH : OFF_A2H;
    const int dst = (blockIdx.y == 0) ? OFF_AGO : OFF_A2GO;
    const float* Hp = g_scratch + src + row * 64;
    float s = 0.f;
#pragma unroll
    for (int q = 0; q < 16; q++) {
        const float4 h = *(const float4*)(Hp + q * 4);
        s += h.x * pws[q * 4] + h.y * pws[q * 4 + 1] +
             h.z * pws[q * 4 + 2] + h.w * pws[q * 4 + 3];
    }
    g_scratch[dst + row] = s + pb[0];
}

// ---------------------------------------------------------------------------
// Orchestration
// ---------------------------------------------------------------------------
extern "C" void kernel_launch(void* const* d_in, const int* in_sizes, int n_in,
                              void* d_out, int out_size) {
    (void)in_sizes; (void)n_in; (void)out_size;
    const float* x   = (const float*)d_in[0];
    const float* y   = (const float*)d_in[1];
    const float* emb = (const float*)d_in[2];
    const float* egW = (const float*)d_in[3];
    const float* egb = (const float*)d_in[4];
    const float* euW = (const float*)d_in[5];
    const float* eub = (const float*)d_in[6];
    const float* dgW = (const float*)d_in[7];
    const float* dgb = (const float*)d_in[8];
    const float* duW = (const float*)d_in[9];
    const float* dub = (const float*)d_in[10];
    const float* pW  = (const float*)d_in[11];
    const float* pb  = (const float*)d_in[12];
    float* out = (float*)d_out;

    build_A<<<1024, 256>>>(emb);
    // M2 = rn(2*A@A - I) into S rows 1024-2047 (only A rows as the A-side)
    tf32_supp5<<<dim3(8, 8), 256>>>(OFF_S, OFF_M2, 1024, 2);
    make_XY<<<3072, 256>>>(x, y);
    zero_state<<<20480, 256>>>();

    const dim3 gX(6, 16);    // stacked [2048,768] outputs
    const dim3 gH(32, 16);   // stacked [2048,4096] outputs

    // Support-propagated exogenous inputs for all timesteps (stacked: [AX;T2X]).
    tf32_supp5<<<gX, 256>>>(OFF_X, OFF_AX, 768, 0);
    tf32_supp5<<<gX, 256>>>(OFF_Y, OFF_AY, 768, 0);

    // ---------------- Encoder ----------------
    for (int t = 0; t < T_; t++) {
        // t=0: H == 0, so AH/T2H == 0 (pre-zeroed) — skip the support GEMM.
        if (t > 0)
            tf32_supp5<<<gH, 256>>>(OFF_H, OFF_AH, 4096, 0);   // [AH; T2H]
        gcn_gate2<1><<<512, 256>>>(OFF_H, OFF_AH, OFF_A2H,
                                   OFF_X, OFF_AX, OFF_A2X,
                                   0, 0, 0, 768, t * 64, 0, 0,
                                   egW, egb, OFF_H, OFF_ZH, OFF_R);
        // t=0: ZH == z*0 == 0, so AZH/T2ZH == 0 (pre-zeroed) — skip.
        if (t > 0)
            tf32_supp5<<<gH, 256>>>(OFF_ZH, OFF_AZH, 4096, 0); // [AZH; T2ZH]
        gcn_upd2<1><<<512, 256>>>(OFF_ZH, OFF_AZH, OFF_A2ZH,
                                  OFF_X, OFF_AX, OFF_A2X,
                                  0, 0, 0, 768, t * 64, 0, 0,
                                  euW, eub, OFF_H, OFF_R);
    }

    // ---------------- Decoder ----------------
    for (int t = 0; t < HOR_; t++) {
        tf32_supp5<<<gH, 256>>>(OFF_H, OFF_AH, 4096, 0);
        if (t > 0) {
            proj_aux<<<dim3(256, 2), 256>>>(pW, pb);
        }
        gcn_gate2<2><<<512, 256>>>(OFF_H, OFF_AH, OFF_A2H,
                                   OFF_GO, OFF_AGO, OFF_A2GO,
                                   OFF_Y, OFF_AY, OFF_A2Y,
                                   64, 0, 768, t * 64,
                                   dgW, dgb, OFF_H, OFF_ZH, OFF_R);
        tf32_supp5<<<gH, 256>>>(OFF_ZH, OFF_AZH, 4096, 0);
        gcn_upd2<2><<<512, 256>>>(OFF_ZH, OFF_AZH, OFF_A2ZH,
                                  OFF_GO, OFF_AGO, OFF_A2GO,
                                  OFF_Y, OFF_AY, OFF_A2Y,
                                  64, 0, 768, t * 64,
                                  duW, dub, OFF_H, OFF_R);
        proj_kernel<<<256, 256>>>(pW, pb, t, out);
    }
}